// round 3
// baseline (speedup 1.0000x reference)
#include <cuda_runtime.h>

typedef unsigned long long ull;

// Problem constants: B=2, N=1024, T=64, H=64
#define NN 1024
#define HH 64

// Scratch (allocation-free rule: __device__ globals)
__device__ float g_p[2 * HH * NN];   // [b][h][n]
__device__ float g_q[2 * HH * NN];   // [b][h][n]
__device__ float g_U[NN];
__device__ float g_V[NN];
__device__ float g_wq[2 * HH];       // duplicated packed 0.2475*W2[h] pairs
__device__ float g_pv[NN * 16];      // per-(row, col-tile) partial max value
__device__ int   g_pi[NN * 16];      // per-(row, col-tile) partial argmax j

// ---- packed f32x2 helpers (Blackwell FFMA2 path) ----
__device__ __forceinline__ ull add_f32x2(ull a, ull b) {
    ull d; asm("add.rn.f32x2 %0, %1, %2;" : "=l"(d) : "l"(a), "l"(b)); return d;
}
__device__ __forceinline__ ull fma_f32x2(ull a, ull b, ull c) {
    ull d; asm("fma.rn.f32x2 %0, %1, %2, %3;" : "=l"(d) : "l"(a), "l"(b), "l"(c)); return d;
}

// ---------------------------------------------------------------------------
// Kernel 1: per-node projections. 128 blocks x 512 threads, 8 nodes/block.
// Thread = (hh = tid>>3, n = tid&7): computes p,q for one (h, node) over both
// batches. Direct coalesced-sector stores (no staging).
//   p[b,h,n] = sum_t x[b,n,t]*W1[h,t]
//   q[b,h,n] = sum_t x[b,n,t]*W1[h,64+t] + b1[h]
//   U[n] = 0.2525*sum_{b,h} w2[h]*p ;  V[n] = 0.2525*sum_{b,h} w2[h]*q + b2
// ---------------------------------------------------------------------------
__global__ void __launch_bounds__(512) k1_proj(
    const float* __restrict__ x, const float* __restrict__ W1,
    const float* __restrict__ b1, const float* __restrict__ W2,
    const float* __restrict__ b2) {
    __shared__ __align__(16) float sW[64][132];    // pitch 132: conflict-free f4
    __shared__ __align__(16) float sx[2][8][68];   // pitch 68: conflict-free f4
    __shared__ float sred[2][64][9];               // U/V partials [sel][h][n]

    const int tid = threadIdx.x;
    const int n0 = blockIdx.x * 8;
    const int hh = tid >> 3;      // 0..63
    const int n  = tid & 7;       // 0..7

    if (blockIdx.x == 0 && tid < 64) {
        float w = 0.2475f * W2[tid];
        g_wq[2 * tid] = w; g_wq[2 * tid + 1] = w;
    }

    #pragma unroll
    for (int k = 0; k < 16; ++k) {            // W1: 8192 floats
        int l = k * 512 + tid;
        sW[l >> 7][l & 127] = W1[l];
    }
    #pragma unroll
    for (int k = 0; k < 2; ++k) {             // x: 1024 floats
        int l = k * 512 + tid;
        int b = l >> 9, node = (l >> 6) & 7, t = l & 63;
        sx[b][node][t] = x[((b << 10) + n0 + node) * 64 + t];
    }
    __syncthreads();

    float p0 = 0.f, p1 = 0.f, q0 = 0.f, q1 = 0.f;
    #pragma unroll 4
    for (int t = 0; t < 64; t += 4) {
        float4 wa = *(const float4*)&sW[hh][t];
        float4 wb = *(const float4*)&sW[hh][64 + t];
        float4 xa = *(const float4*)&sx[0][n][t];
        float4 xb = *(const float4*)&sx[1][n][t];
        p0 = fmaf(xa.x, wa.x, p0); p0 = fmaf(xa.y, wa.y, p0);
        p0 = fmaf(xa.z, wa.z, p0); p0 = fmaf(xa.w, wa.w, p0);
        p1 = fmaf(xb.x, wa.x, p1); p1 = fmaf(xb.y, wa.y, p1);
        p1 = fmaf(xb.z, wa.z, p1); p1 = fmaf(xb.w, wa.w, p1);
        q0 = fmaf(xa.x, wb.x, q0); q0 = fmaf(xa.y, wb.y, q0);
        q0 = fmaf(xa.z, wb.z, q0); q0 = fmaf(xa.w, wb.w, q0);
        q1 = fmaf(xb.x, wb.x, q1); q1 = fmaf(xb.y, wb.y, q1);
        q1 = fmaf(xb.z, wb.z, q1); q1 = fmaf(xb.w, wb.w, q1);
    }
    float bb = __ldg(&b1[hh]);
    q0 += bb; q1 += bb;

    // direct stores: 8 consecutive n per h -> full 32B sectors
    g_p[hh * 1024 + n0 + n]          = p0;
    g_p[(64 + hh) * 1024 + n0 + n]   = p1;
    g_q[hh * 1024 + n0 + n]          = q0;
    g_q[(64 + hh) * 1024 + n0 + n]   = q1;

    float w2h = __ldg(&W2[hh]);
    sred[0][hh][n] = w2h * (p0 + p1);
    sred[1][hh][n] = w2h * (q0 + q1);
    __syncthreads();
    if (tid < 16) {
        int sel = tid >> 3, nn2 = tid & 7;
        float acc = 0.f;
        #pragma unroll 8
        for (int k = 0; k < 64; ++k) acc += sred[sel][k][nn2];
        if (sel == 0) g_U[n0 + nn2] = 0.2525f * acc;
        else          g_V[n0 + nn2] = 0.2525f * acc + b2[0];
    }
}

// ---------------------------------------------------------------------------
// Kernel 2: pairwise |z| accumulation (packed f32x2) + fused gumbel/argmax.
//   logit[i,j] = sum_{b,h} 0.2475*w2[h]*|p[b,i,h]+q[b,j,h]| + U[i] + V[j]
//   v[i,j] = logit + gumbel(gu[i,j]); per-row-tile argmax -> partials.
//   Writes ZEROS to out tile (final one-hot ones set by k3_fin).
// Grid 16x16, block 16x16 threads, 4x4 register tile (packed along i-pairs).
// ---------------------------------------------------------------------------
__global__ void __launch_bounds__(256) k2_pair(const float* __restrict__ gu,
                                               float* __restrict__ out) {
    __shared__ __align__(16) float ps[64][64];     // [h][i]
    __shared__ __align__(16) float qsd[64][128];   // [h][2j] duplicated

    const int tx = threadIdx.x, ty = threadIdx.y;
    const int tid = ty * 16 + tx;
    const int i0 = blockIdx.y * 64, j0 = blockIdx.x * 64;
    const ull MASK = 0x7FFFFFFF7FFFFFFFULL;

    ull acc[2][4];
    #pragma unroll
    for (int r = 0; r < 2; ++r)
        #pragma unroll
        for (int c = 0; c < 4; ++c) acc[r][c] = 0ULL;

    #pragma unroll
    for (int b = 0; b < 2; ++b) {
        const float* pg = g_p + b * 64 * 1024;
        const float* qg = g_q + b * 64 * 1024;
        __syncthreads();
        #pragma unroll
        for (int k = 0; k < 4; ++k) {           // ps fill: float4 coalesced
            int l = k * 256 + tid;
            int hh = l >> 4, io = (l & 15) << 2;
            *(float4*)&ps[hh][io] = *(const float4*)&pg[hh * 1024 + i0 + io];
        }
        #pragma unroll
        for (int k = 0; k < 16; ++k) {          // qsd fill: duplicate pairs
            int l = k * 256 + tid;
            int hh = l >> 6, j = l & 63;
            float v = qg[hh * 1024 + j0 + j];
            *(float2*)&qsd[hh][2 * j] = make_float2(v, v);
        }
        __syncthreads();

        #pragma unroll 8
        for (int h = 0; h < 64; ++h) {
            ull wq = __ldg((const ull*)(g_wq + 2 * h));
            ulonglong2 ppv = *(const ulonglong2*)&ps[h][ty << 2];
            ulonglong2 qA  = *(const ulonglong2*)&qsd[h][tx << 3];
            ulonglong2 qB  = *(const ulonglong2*)&qsd[h][(tx << 3) + 4];
            ull pr[2] = {ppv.x, ppv.y};
            ull qc[4] = {qA.x, qA.y, qB.x, qB.y};
            #pragma unroll
            for (int r = 0; r < 2; ++r)
                #pragma unroll
                for (int c = 0; c < 4; ++c) {
                    ull z = add_f32x2(pr[r], qc[c]);
                    z &= MASK;
                    acc[r][c] = fma_f32x2(wq, z, acc[r][c]);
                }
        }
    }

    float u[4], v[4];
    #pragma unroll
    for (int r = 0; r < 4; ++r) u[r] = g_U[i0 + (ty << 2) + r];
    #pragma unroll
    for (int c = 0; c < 4; ++c) v[c] = g_V[j0 + (tx << 2) + c];

    // unpack packed accumulators into per-row logits vrow[r][c]
    float vrow[4][4];
    #pragma unroll
    for (int r2 = 0; r2 < 2; ++r2) {
        #pragma unroll
        for (int c = 0; c < 4; ++c) {
            float2 a = *(float2*)&acc[r2][c];
            vrow[r2 * 2][c]     = a.x + u[r2 * 2] + v[c];
            vrow[r2 * 2 + 1][c] = a.y + u[r2 * 2 + 1] + v[c];
        }
    }

    // zero-fill this out tile (final ones written by k3_fin)
    const float4 z4 = make_float4(0.f, 0.f, 0.f, 0.f);
    #pragma unroll
    for (int r = 0; r < 4; ++r)
        *(float4*)&out[(i0 + (ty << 2) + r) * 1024 + j0 + (tx << 2)] = z4;

    // gumbel + per-row argmax across the 16 tx lanes (shfl.bfly, 16-lane groups)
    #pragma unroll
    for (int r = 0; r < 4; ++r) {
        const int row = i0 + (ty << 2) + r;
        float4 uu = *(const float4*)&gu[row * 1024 + j0 + (tx << 2)];
        float gq[4];
        gq[0] = -__logf(-__logf(uu.x + 1e-10f) + 1e-10f);
        gq[1] = -__logf(-__logf(uu.y + 1e-10f) + 1e-10f);
        gq[2] = -__logf(-__logf(uu.z + 1e-10f) + 1e-10f);
        gq[3] = -__logf(-__logf(uu.w + 1e-10f) + 1e-10f);
        float bv = -3.0e38f; int bj = 1 << 30;
        #pragma unroll
        for (int c = 0; c < 4; ++c) {
            float val = vrow[r][c] + gq[c];
            int j = j0 + (tx << 2) + c;
            if (val > bv || (val == bv && j < bj)) { bv = val; bj = j; }
        }
        #pragma unroll
        for (int m = 1; m < 16; m <<= 1) {
            float ov = __shfl_xor_sync(0xffffffffu, bv, m);
            int   oj = __shfl_xor_sync(0xffffffffu, bj, m);
            if (ov > bv || (ov == bv && oj < bj)) { bv = ov; bj = oj; }
        }
        if (tx == 0) {
            g_pv[row * 16 + blockIdx.x] = bv;
            g_pi[row * 16 + blockIdx.x] = bj;
        }
    }
}

// ---------------------------------------------------------------------------
// Kernel 3: reduce 16 tile-partials per row, scatter the one-hot 1.0s.
// ---------------------------------------------------------------------------
__global__ void __launch_bounds__(256) k3_fin(float* __restrict__ out) {
    const int i = blockIdx.x * 256 + threadIdx.x;   // row, grid 4x256 = 1024
    float bv = -3.0e38f; int bj = 1 << 30;
    #pragma unroll
    for (int k = 0; k < 16; ++k) {
        float v = g_pv[i * 16 + k];
        int   j = g_pi[i * 16 + k];
        if (v > bv || (v == bv && j < bj)) { bv = v; bj = j; }
    }
    out[i * 1024 + bj] = 1.0f;
}

// ---------------------------------------------------------------------------
extern "C" void kernel_launch(void* const* d_in, const int* in_sizes, int n_in,
                              void* d_out, int out_size) {
    const float* x  = (const float*)d_in[0];   // [2,1024,64]
    const float* W1 = (const float*)d_in[1];   // [64,128]
    const float* b1 = (const float*)d_in[2];   // [64]
    const float* W2 = (const float*)d_in[3];   // [1,64]
    const float* b2 = (const float*)d_in[4];   // [1]
    const float* gu = (const float*)d_in[5];   // [1024,1024]
    float* out = (float*)d_out;                // [1024,1024] fp32

    k1_proj<<<128, 512>>>(x, W1, b1, W2, b2);
    k2_pair<<<dim3(16, 16), dim3(16, 16)>>>(gu, out);
    k3_fin<<<4, 256>>>(out);
}

// round 6
// speedup vs baseline: 1.4337x; 1.4337x over previous
#include <cuda_runtime.h>

// Problem constants: B=2, N=1024, T=64, H=64
#define NN 1024
#define HH 64

// Scratch (allocation-free rule: __device__ globals)
// p/q layout: [h][n][b] interleaved -> element (h,n,b) at (h*1024+n)*2+b
__device__ float g_p[2 * HH * NN];
__device__ float g_q[2 * HH * NN];
__device__ float g_U[NN];
__device__ float g_V[NN];
__device__ float g_pv[NN * 16];      // per-(row, col-tile) partial max value
__device__ int   g_pi[NN * 16];      // per-(row, col-tile) partial argmax j

// ---------------------------------------------------------------------------
// Kernel 1: per-node projections. 128 blocks x 512 threads, 8 nodes/block.
// Thread = (hh = tid>>3, n = tid&7).
//   p[h,n,b] = sum_t x[b,n,t]*W1[h,t]
//   q[h,n,b] = sum_t x[b,n,t]*W1[h,64+t] + b1[h]
//   U[n] = 0.2525*sum_{b,h} w2[h]*p ;  V[n] = 0.2525*sum_{b,h} w2[h]*q + b2
// ---------------------------------------------------------------------------
__global__ void __launch_bounds__(512) k1_proj(
    const float* __restrict__ x, const float* __restrict__ W1,
    const float* __restrict__ b1, const float* __restrict__ W2,
    const float* __restrict__ b2) {
    __shared__ __align__(16) float sW[64][132];    // pitch 132: conflict-free f4
    __shared__ __align__(16) float sx[2][8][68];   // pitch 68: conflict-free f4
    __shared__ float sred[2][64][9];               // U/V partials [sel][h][n]

    const int tid = threadIdx.x;
    const int n0 = blockIdx.x * 8;
    const int hh = tid >> 3;      // 0..63
    const int n  = tid & 7;       // 0..7

    #pragma unroll
    for (int k = 0; k < 16; ++k) {            // W1: 8192 floats
        int l = k * 512 + tid;
        sW[l >> 7][l & 127] = W1[l];
    }
    #pragma unroll
    for (int k = 0; k < 2; ++k) {             // x: 1024 floats
        int l = k * 512 + tid;
        int b = l >> 9, node = (l >> 6) & 7, t = l & 63;
        sx[b][node][t] = x[((b << 10) + n0 + node) * 64 + t];
    }
    __syncthreads();

    float p0 = 0.f, p1 = 0.f, q0 = 0.f, q1 = 0.f;
    #pragma unroll 4
    for (int t = 0; t < 64; t += 4) {
        float4 wa = *(const float4*)&sW[hh][t];
        float4 wb = *(const float4*)&sW[hh][64 + t];
        float4 xa = *(const float4*)&sx[0][n][t];
        float4 xb = *(const float4*)&sx[1][n][t];
        p0 = fmaf(xa.x, wa.x, p0); p0 = fmaf(xa.y, wa.y, p0);
        p0 = fmaf(xa.z, wa.z, p0); p0 = fmaf(xa.w, wa.w, p0);
        p1 = fmaf(xb.x, wa.x, p1); p1 = fmaf(xb.y, wa.y, p1);
        p1 = fmaf(xb.z, wa.z, p1); p1 = fmaf(xb.w, wa.w, p1);
        q0 = fmaf(xa.x, wb.x, q0); q0 = fmaf(xa.y, wb.y, q0);
        q0 = fmaf(xa.z, wb.z, q0); q0 = fmaf(xa.w, wb.w, q0);
        q1 = fmaf(xb.x, wb.x, q1); q1 = fmaf(xb.y, wb.y, q1);
        q1 = fmaf(xb.z, wb.z, q1); q1 = fmaf(xb.w, wb.w, q1);
    }
    float bb = __ldg(&b1[hh]);
    q0 += bb; q1 += bb;

    // interleaved float2 stores: threads n=0..7 -> 64B contiguous
    *(float2*)&g_p[(hh * 1024 + n0 + n) * 2] = make_float2(p0, p1);
    *(float2*)&g_q[(hh * 1024 + n0 + n) * 2] = make_float2(q0, q1);

    float w2h = __ldg(&W2[hh]);
    sred[0][hh][n] = w2h * (p0 + p1);
    sred[1][hh][n] = w2h * (q0 + q1);
    __syncthreads();
    if (tid < 16) {
        int sel = tid >> 3, nn2 = tid & 7;
        float acc = 0.f;
        #pragma unroll 8
        for (int k = 0; k < 64; ++k) acc += sred[sel][k][nn2];
        if (sel == 0) g_U[n0 + nn2] = 0.2525f * acc;
        else          g_V[n0 + nn2] = 0.2525f * acc + b2[0];
    }
}

// ---------------------------------------------------------------------------
// Kernel 2: pairwise |z| accumulation (scalar FADD + FFMA|.|) + fused
// gumbel/argmax. h chunked by 32 to fit 32KB static smem.
//   logit[i,j] = sum_{b,h} 0.2475*w2[h]*|p[h,i,b]+q[h,j,b]| + U[i] + V[j]
// Grid 16x16 (64x64 tile), block 16x16 threads, 4i x 4j x 2b per thread.
// ---------------------------------------------------------------------------
__global__ void __launch_bounds__(256) k2_pair(const float* __restrict__ W2,
                                               const float* __restrict__ gu,
                                               float* __restrict__ out) {
    __shared__ __align__(16) float ps[32][128];    // [h][i*2+b] chunk
    __shared__ __align__(16) float qs[32][128];    // [h][j*2+b] chunk
    __shared__ float sw[64];

    const int tx = threadIdx.x, ty = threadIdx.y;
    const int tid = ty * 16 + tx;
    const int i0 = blockIdx.y * 64, j0 = blockIdx.x * 64;

    if (tid < 64) sw[tid] = 0.2475f * W2[tid];

    float acc[4][4];
    #pragma unroll
    for (int r = 0; r < 4; ++r)
        #pragma unroll
        for (int c = 0; c < 4; ++c) acc[r][c] = 0.f;

    #pragma unroll
    for (int hc = 0; hc < 2; ++hc) {
        const int hb = hc * 32;
        const float* __restrict__ pgc = g_p + (hb * 1024 + i0) * 2;
        const float* __restrict__ qgc = g_q + (hb * 1024 + j0) * 2;
        __syncthreads();   // protect prior chunk (and sw on first iter)
        // fill: each tile chunk = 1024 float4, warp covers one h-row (512B)
        #pragma unroll
        for (int k = 0; k < 4; ++k) {
            int l = k * 256 + tid;               // 0..1023
            int hh = l >> 5, f4 = l & 31;
            *(float4*)&ps[hh][f4 << 2] =
                *(const float4*)&pgc[hh * 2048 + (f4 << 2)];
            *(float4*)&qs[hh][f4 << 2] =
                *(const float4*)&qgc[hh * 2048 + (f4 << 2)];
        }
        __syncthreads();

        #pragma unroll 4
        for (int h = 0; h < 32; ++h) {
            float w = sw[hb + h];
            float4 pA = *(const float4*)&ps[h][ty << 3];        // i r=0,1
            float4 pB = *(const float4*)&ps[h][(ty << 3) + 4];  // i r=2,3
            float4 qA = *(const float4*)&qs[h][tx << 3];
            float4 qB = *(const float4*)&qs[h][(tx << 3) + 4];
            float pv[8] = {pA.x, pA.y, pA.z, pA.w, pB.x, pB.y, pB.z, pB.w};
            float qv[8] = {qA.x, qA.y, qA.z, qA.w, qB.x, qB.y, qB.z, qB.w};
            #pragma unroll
            for (int r = 0; r < 4; ++r)
                #pragma unroll
                for (int c = 0; c < 4; ++c) {
                    float z0 = pv[2 * r]     + qv[2 * c];        // batch 0
                    float z1 = pv[2 * r + 1] + qv[2 * c + 1];    // batch 1
                    acc[r][c] = fmaf(w, fabsf(z0), acc[r][c]);
                    acc[r][c] = fmaf(w, fabsf(z1), acc[r][c]);
                }
        }
    }

    float u[4], v[4];
    #pragma unroll
    for (int r = 0; r < 4; ++r) u[r] = g_U[i0 + (ty << 2) + r];
    #pragma unroll
    for (int c = 0; c < 4; ++c) v[c] = g_V[j0 + (tx << 2) + c];

    float vrow[4][4];
    #pragma unroll
    for (int r = 0; r < 4; ++r)
        #pragma unroll
        for (int c = 0; c < 4; ++c)
            vrow[r][c] = acc[r][c] + u[r] + v[c];

    // zero-fill this out tile (final ones written by k3_fin)
    const float4 z4 = make_float4(0.f, 0.f, 0.f, 0.f);
    #pragma unroll
    for (int r = 0; r < 4; ++r)
        *(float4*)&out[(i0 + (ty << 2) + r) * 1024 + j0 + (tx << 2)] = z4;

    // gumbel + per-row argmax across the 16 tx lanes (xor-shfl in half-warp)
    #pragma unroll
    for (int r = 0; r < 4; ++r) {
        const int row = i0 + (ty << 2) + r;
        float4 uu = *(const float4*)&gu[row * 1024 + j0 + (tx << 2)];
        float gq[4];
        gq[0] = -__logf(-__logf(uu.x + 1e-10f) + 1e-10f);
        gq[1] = -__logf(-__logf(uu.y + 1e-10f) + 1e-10f);
        gq[2] = -__logf(-__logf(uu.z + 1e-10f) + 1e-10f);
        gq[3] = -__logf(-__logf(uu.w + 1e-10f) + 1e-10f);
        float bv = -3.0e38f; int bj = 1 << 30;
        #pragma unroll
        for (int c = 0; c < 4; ++c) {
            float val = vrow[r][c] + gq[c];
            int j = j0 + (tx << 2) + c;
            if (val > bv || (val == bv && j < bj)) { bv = val; bj = j; }
        }
        #pragma unroll
        for (int m = 1; m < 16; m <<= 1) {
            float ov = __shfl_xor_sync(0xffffffffu, bv, m);
            int   oj = __shfl_xor_sync(0xffffffffu, bj, m);
            if (ov > bv || (ov == bv && oj < bj)) { bv = ov; bj = oj; }
        }
        if (tx == 0) {
            g_pv[row * 16 + blockIdx.x] = bv;
            g_pi[row * 16 + blockIdx.x] = bj;
        }
    }
}

// ---------------------------------------------------------------------------
// Kernel 3: reduce 16 tile-partials per row, scatter the one-hot 1.0s.
// ---------------------------------------------------------------------------
__global__ void __launch_bounds__(256) k3_fin(float* __restrict__ out) {
    const int i = blockIdx.x * 256 + threadIdx.x;   // row, grid 4x256
    float bv = -3.0e38f; int bj = 1 << 30;
    #pragma unroll
    for (int k4 = 0; k4 < 4; ++k4) {
        float4 v4 = *(const float4*)&g_pv[i * 16 + k4 * 4];
        int4   j4 = *(const int4*)&g_pi[i * 16 + k4 * 4];
        float vv[4] = {v4.x, v4.y, v4.z, v4.w};
        int   jj[4] = {j4.x, j4.y, j4.z, j4.w};
        #pragma unroll
        for (int k = 0; k < 4; ++k)
            if (vv[k] > bv || (vv[k] == bv && jj[k] < bj)) { bv = vv[k]; bj = jj[k]; }
    }
    out[i * 1024 + bj] = 1.0f;
}

// ---------------------------------------------------------------------------
extern "C" void kernel_launch(void* const* d_in, const int* in_sizes, int n_in,
                              void* d_out, int out_size) {
    const float* x  = (const float*)d_in[0];   // [2,1024,64]
    const float* W1 = (const float*)d_in[1];   // [64,128]
    const float* b1 = (const float*)d_in[2];   // [64]
    const float* W2 = (const float*)d_in[3];   // [1,64]
    const float* b2 = (const float*)d_in[4];   // [1]
    const float* gu = (const float*)d_in[5];   // [1024,1024]
    float* out = (float*)d_out;                // [1024,1024] fp32

    k1_proj<<<128, 512>>>(x, W1, b1, W2, b2);
    k2_pair<<<dim3(16, 16), dim3(16, 16)>>>(W2, gu, out);
    k3_fin<<<4, 256>>>(out);
}